// round 1
// baseline (speedup 1.0000x reference)
#include <cuda_runtime.h>
#include <cuda_bf16.h>

#define DPAR   1024
#define KSEL   32
#define NITER  12
#define CHUNKS 8          // 8 x float4 per lane = 32 elements/lane

__device__ __align__(16) float g_mean[DPAR];
__device__ __align__(16) float g_invstd[DPAR];
__device__ float g_alpha;
__device__ float g_sigma;

__global__ void prep_kernel(const float* __restrict__ ema_mean,
                            const float* __restrict__ ema_sq,
                            const float* __restrict__ log_alpha,
                            const float* __restrict__ log_sigma, int d) {
    int i = blockIdx.x * blockDim.x + threadIdx.x;
    if (i < d) {
        float m = ema_mean[i];
        float v = ema_sq[i] - m * m;
        v = fmaxf(v, 1e-6f);
        g_mean[i]   = m;
        g_invstd[i] = rsqrtf(v);
    }
    if (i == 0) {
        g_alpha = expf(log_alpha[0]);
        g_sigma = expf(log_sigma[0]);
    }
}

__global__ __launch_bounds__(256, 4) void gelu_topk_kernel(
        const float4* __restrict__ x4, float4* __restrict__ out4, int rows) {
    int gw   = (blockIdx.x * 256 + threadIdx.x) >> 5;   // one warp per row
    int lane = threadIdx.x & 31;
    if (gw >= rows) return;

    const float4* xr   = x4  + (size_t)gw * (DPAR / 4);
    float4*       orow = out4 + (size_t)gw * (DPAR / 4);
    const float4* m4 = reinterpret_cast<const float4*>(g_mean);
    const float4* s4 = reinterpret_cast<const float4*>(g_invstd);

    // ---- pass 1: z = |x - mu| * invstd, kept in registers; per-thread max ----
    float z[CHUNKS][4];
    float tmax = 0.0f;   // z >= 0
    #pragma unroll
    for (int c = 0; c < CHUNKS; c++) {
        int idx = c * 32 + lane;
        float4 xv = __ldg(xr + idx);
        float4 mu = __ldg(m4 + idx);
        float4 iv = __ldg(s4 + idx);
        z[c][0] = fabsf((xv.x - mu.x) * iv.x);
        z[c][1] = fabsf((xv.y - mu.y) * iv.y);
        z[c][2] = fabsf((xv.z - mu.z) * iv.z);
        z[c][3] = fabsf((xv.w - mu.w) * iv.w);
        tmax = fmaxf(tmax,
               fmaxf(fmaxf(z[c][0], z[c][1]), fmaxf(z[c][2], z[c][3])));
    }

    // ---- bracket the K-th largest:  lo = min over lanes of per-lane max
    //      (min of any 32-element subset <= 32nd order statistic), hi = row max
    float rmax = tmax, tmin = tmax;
    #pragma unroll
    for (int off = 16; off; off >>= 1) {
        rmax = fmaxf(rmax, __shfl_xor_sync(0xffffffffu, rmax, off));
        tmin = fminf(tmin, __shfl_xor_sync(0xffffffffu, tmin, off));
    }
    float lo = tmin, hi = rmax;

    // ---- count-based bisection on the threshold (warp-local, REDUX.SUM) ----
    #pragma unroll
    for (int it = 0; it < NITER; ++it) {
        float T = 0.5f * (lo + hi);
        int cnt = 0;
        #pragma unroll
        for (int c = 0; c < CHUNKS; c++) {
            cnt += (z[c][0] > T) + (z[c][1] > T)
                 + (z[c][2] > T) + (z[c][3] > T);
        }
        cnt = __reduce_add_sync(0xffffffffu, cnt);
        if (cnt >= KSEL) lo = T; else hi = T;
    }

    // ---- top-K sum: exact part above hi + boundary elements ~ mid(lo,hi) ----
    float hT = hi;
    float ssum = 0.0f;
    int   chi  = 0;
    #pragma unroll
    for (int c = 0; c < CHUNKS; c++) {
        #pragma unroll
        for (int j = 0; j < 4; j++) {
            if (z[c][j] > hT) { ssum += z[c][j]; chi++; }
        }
    }
    #pragma unroll
    for (int off = 16; off; off >>= 1)
        ssum += __shfl_xor_sync(0xffffffffu, ssum, off);
    chi = __reduce_add_sync(0xffffffffu, chi);

    float Tmid = 0.5f * (lo + hi);
    float surp = (ssum + (float)(KSEL - chi) * Tmid) * (1.0f / (float)KSEL);
    float gate = 1.0f + g_alpha * tanhf(g_sigma * surp);

    // ---- pass 2: exact erf-GELU * gate (x reloaded — L1 hit) ----
    const float inv_sqrt2 = 0.70710678118654752f;
    #pragma unroll
    for (int c = 0; c < CHUNKS; c++) {
        int idx = c * 32 + lane;
        float4 xv = __ldg(xr + idx);
        float4 o;
        o.x = 0.5f * xv.x * (1.0f + erff(xv.x * inv_sqrt2)) * gate;
        o.y = 0.5f * xv.y * (1.0f + erff(xv.y * inv_sqrt2)) * gate;
        o.z = 0.5f * xv.z * (1.0f + erff(xv.z * inv_sqrt2)) * gate;
        o.w = 0.5f * xv.w * (1.0f + erff(xv.w * inv_sqrt2)) * gate;
        orow[idx] = o;
    }
}

extern "C" void kernel_launch(void* const* d_in, const int* in_sizes, int n_in,
                              void* d_out, int out_size) {
    const float* x         = (const float*)d_in[0];
    const float* log_alpha = (const float*)d_in[1];
    const float* log_sigma = (const float*)d_in[2];
    const float* ema_mean  = (const float*)d_in[3];
    const float* ema_sq    = (const float*)d_in[4];
    float* out = (float*)d_out;

    int d    = in_sizes[3];          // 1024
    int rows = in_sizes[0] / d;      // 32768

    prep_kernel<<<(d + 255) / 256, 256>>>(ema_mean, ema_sq, log_alpha, log_sigma, d);

    int blocks = (rows + 7) / 8;     // 8 warps (rows) per 256-thread block
    gelu_topk_kernel<<<blocks, 256>>>(
        reinterpret_cast<const float4*>(x),
        reinterpret_cast<float4*>(out), rows);
}

// round 3
// speedup vs baseline: 1.3030x; 1.3030x over previous
#include <cuda_runtime.h>
#include <cuda_fp16.h>
#include <cuda_bf16.h>

#define DPAR   1024
#define KSEL   32
#define NITER  10
#define CHUNKS 8          // 8 x float4 per lane = 32 elements/lane
#define H2N    16         // 16 half2 = 32 z values per lane

__device__ __align__(16) float g_mean[DPAR];
__device__ __align__(16) float g_invstd[DPAR];
__device__ float g_alpha;
__device__ float g_sigma;

__global__ void prep_kernel(const float* __restrict__ ema_mean,
                            const float* __restrict__ ema_sq,
                            const float* __restrict__ log_alpha,
                            const float* __restrict__ log_sigma, int d) {
    int i = blockIdx.x * blockDim.x + threadIdx.x;
    if (i < d) {
        float m = ema_mean[i];
        float v = ema_sq[i] - m * m;
        v = fmaxf(v, 1e-6f);
        g_mean[i]   = m;
        g_invstd[i] = rsqrtf(v);
    }
    if (i == 0) {
        g_alpha = expf(log_alpha[0]);
        g_sigma = expf(log_sigma[0]);
    }
}

__global__ __launch_bounds__(256, 5) void gelu_topk_kernel(
        const float4* __restrict__ x4, float4* __restrict__ out4, int rows) {
    int gw   = (blockIdx.x * 256 + threadIdx.x) >> 5;   // one warp per row
    int lane = threadIdx.x & 31;
    if (gw >= rows) return;

    const float4* xr   = x4   + (size_t)gw * (DPAR / 4) + lane;
    float4*       orow = out4 + (size_t)gw * (DPAR / 4) + lane;
    const float4* m4 = reinterpret_cast<const float4*>(g_mean)   + lane;
    const float4* s4 = reinterpret_cast<const float4*>(g_invstd) + lane;

    // ---- pass 1: z = |x - mu| * invstd (fp32), pack into half2; per-thread max
    __half2 z2[H2N];
    float tmax = 0.0f;   // z >= 0
    #pragma unroll
    for (int c = 0; c < CHUNKS; c++) {
        float4 xv = __ldg(xr + c * 32);
        float4 mu = __ldg(m4 + c * 32);
        float4 iv = __ldg(s4 + c * 32);
        float a = fabsf((xv.x - mu.x) * iv.x);
        float b = fabsf((xv.y - mu.y) * iv.y);
        float cc = fabsf((xv.z - mu.z) * iv.z);
        float dd = fabsf((xv.w - mu.w) * iv.w);
        z2[c * 2 + 0] = __floats2half2_rn(a, b);
        z2[c * 2 + 1] = __floats2half2_rn(cc, dd);
        tmax = fmaxf(tmax, fmaxf(fmaxf(a, b), fmaxf(cc, dd)));
    }

    // ---- bracket the K-th largest:
    //      lo = min over lanes of per-lane max (any 32-subset min <= 32nd stat)
    //      hi = row max
    float rmax = tmax, tmin = tmax;
    #pragma unroll
    for (int off = 16; off; off >>= 1) {
        rmax = fmaxf(rmax, __shfl_xor_sync(0xffffffffu, rmax, off));
        tmin = fminf(tmin, __shfl_xor_sync(0xffffffffu, tmin, off));
    }
    float lo = tmin, hi = rmax;

    // ---- count-based bisection, packed half2 compares + REDUX.SUM ----
    #pragma unroll
    for (int it = 0; it < NITER; ++it) {
        float T = 0.5f * (lo + hi);
        __half2 T2  = __float2half2_rn(T);
        __half2 acc = __float2half2_rn(0.0f);
        #pragma unroll
        for (int i = 0; i < H2N; i++)
            acc = __hadd2(acc, __hgt2(z2[i], T2));     // true -> 1.0, false -> 0.0
        int cnt = (int)(__low2float(acc) + __high2float(acc));
        cnt = __reduce_add_sync(0xffffffffu, cnt);
        if (cnt >= KSEL) lo = T; else hi = T;
    }

    // ---- top-K sum: exact-ish part above hi + boundary elems ~ mid(lo,hi) ----
    {
        __half2 hi2  = __float2half2_rn(hi);
        __half2 sacc = __float2half2_rn(0.0f);
        __half2 cacc = __float2half2_rn(0.0f);
        #pragma unroll
        for (int i = 0; i < H2N; i++) {
            __half2 m = __hgt2(z2[i], hi2);
            sacc = __hfma2(m, z2[i], sacc);
            cacc = __hadd2(cacc, m);
        }
        float ssum = __low2float(sacc) + __high2float(sacc);
        int   chi  = (int)(__low2float(cacc) + __high2float(cacc));
        #pragma unroll
        for (int off = 16; off; off >>= 1)
            ssum += __shfl_xor_sync(0xffffffffu, ssum, off);
        chi = __reduce_add_sync(0xffffffffu, chi);

        float Tmid = 0.5f * (lo + hi);
        float surp = (ssum + (float)(KSEL - chi) * Tmid) * (1.0f / (float)KSEL);
        float gate = 1.0f + g_alpha * tanhf(g_sigma * surp);
        float gh   = 0.5f * gate;   // fold the GELU 0.5 into the gate

        // ---- pass 2: exact erf-GELU * gate (x reloaded — L1 hit) ----
        const float inv_sqrt2 = 0.70710678118654752f;
        #pragma unroll
        for (int c = 0; c < CHUNKS; c++) {
            float4 xv = __ldg(xr + c * 32);
            float4 o;
            o.x = gh * xv.x * (1.0f + erff(xv.x * inv_sqrt2));
            o.y = gh * xv.y * (1.0f + erff(xv.y * inv_sqrt2));
            o.z = gh * xv.z * (1.0f + erff(xv.z * inv_sqrt2));
            o.w = gh * xv.w * (1.0f + erff(xv.w * inv_sqrt2));
            orow[c * 32] = o;
        }
    }
}

extern "C" void kernel_launch(void* const* d_in, const int* in_sizes, int n_in,
                              void* d_out, int out_size) {
    const float* x         = (const float*)d_in[0];
    const float* log_alpha = (const float*)d_in[1];
    const float* log_sigma = (const float*)d_in[2];
    const float* ema_mean  = (const float*)d_in[3];
    const float* ema_sq    = (const float*)d_in[4];
    float* out = (float*)d_out;

    int d    = in_sizes[3];          // 1024
    int rows = in_sizes[0] / d;      // 32768

    prep_kernel<<<(d + 255) / 256, 256>>>(ema_mean, ema_sq, log_alpha, log_sigma, d);

    int blocks = (rows + 7) / 8;     // 8 warps (rows) per 256-thread block
    gelu_topk_kernel<<<blocks, 256>>>(
        reinterpret_cast<const float4*>(x),
        reinterpret_cast<float4*>(out), rows);
}

// round 4
// speedup vs baseline: 1.3374x; 1.0264x over previous
#include <cuda_runtime.h>
#include <cuda_fp16.h>
#include <cuda_bf16.h>

#define DPAR   1024
#define KSEL   32
#define NITER  7
#define CHUNKS 8          // 8 x float4 per lane = 32 elements/lane
#define H2N    16         // 16 half2 = 32 z values per lane

__device__ __align__(16) float g_mean[DPAR];
__device__ __align__(16) float g_invstd[DPAR];
__device__ float g_alpha;
__device__ float g_sigma;

__global__ void prep_kernel(const float* __restrict__ ema_mean,
                            const float* __restrict__ ema_sq,
                            const float* __restrict__ log_alpha,
                            const float* __restrict__ log_sigma, int d) {
    int i = blockIdx.x * blockDim.x + threadIdx.x;
    if (i < d) {
        float m = ema_mean[i];
        float v = ema_sq[i] - m * m;
        v = fmaxf(v, 1e-6f);
        g_mean[i]   = m;
        g_invstd[i] = rsqrtf(v);
    }
    if (i == 0) {
        g_alpha = expf(log_alpha[0]);
        g_sigma = expf(log_sigma[0]);
    }
}

// Phi(x) = 0.5*(1+erf(x/sqrt2)) via A&S 7.1.26 erfc (abs err ~1.5e-7).
// Returns the multiplier w such that gelu(x) = x * w.
__device__ __forceinline__ float gelu_phi(float x) {
    const float inv_sqrt2 = 0.70710678118654752f;
    float u  = x * inv_sqrt2;
    float au = fabsf(u);
    float t  = __fdividef(1.0f, fmaf(0.3275911f, au, 1.0f));
    float P  = t * fmaf(t, fmaf(t, fmaf(t, fmaf(t, 1.061405429f, -1.453152027f),
                                        1.421413741f), -0.284496736f), 0.254829592f);
    float e  = __expf(-u * u);
    float he = 0.5f * (P * e);            // 0.5*erfc(|u|)
    return (u >= 0.0f) ? (1.0f - he) : he;
}

__global__ __launch_bounds__(256, 5) void gelu_topk_kernel(
        const float4* __restrict__ x4, float4* __restrict__ out4, int rows) {
    int gw   = (blockIdx.x * 256 + threadIdx.x) >> 5;   // one warp per row
    int lane = threadIdx.x & 31;
    if (gw >= rows) return;

    const float4* xr   = x4   + (size_t)gw * (DPAR / 4) + lane;
    float4*       orow = out4 + (size_t)gw * (DPAR / 4) + lane;
    const float4* m4 = reinterpret_cast<const float4*>(g_mean)   + lane;
    const float4* s4 = reinterpret_cast<const float4*>(g_invstd) + lane;

    // ---- pass 1: z = |x - mu| * invstd (fp32), pack into half2; packed max ----
    __half2 z2[H2N];
    __half2 tmax2 = __float2half2_rn(0.0f);
    #pragma unroll
    for (int c = 0; c < CHUNKS; c++) {
        float4 xv = __ldg(xr + c * 32);
        float4 mu = __ldg(m4 + c * 32);
        float4 iv = __ldg(s4 + c * 32);
        float a  = fabsf((xv.x - mu.x) * iv.x);
        float b  = fabsf((xv.y - mu.y) * iv.y);
        float cc = fabsf((xv.z - mu.z) * iv.z);
        float dd = fabsf((xv.w - mu.w) * iv.w);
        z2[c * 2 + 0] = __floats2half2_rn(a, b);
        z2[c * 2 + 1] = __floats2half2_rn(cc, dd);
        tmax2 = __hmax2(tmax2, __hmax2(z2[c * 2 + 0], z2[c * 2 + 1]));
    }
    float tmax = fmaxf(__low2float(tmax2), __high2float(tmax2));

    // ---- bracket the K-th largest:
    //      lo = min over lanes of per-lane max (any 32-subset min <= 32nd stat)
    //      hi = row max
    float rmax = tmax, tmin = tmax;
    #pragma unroll
    for (int off = 16; off; off >>= 1) {
        rmax = fmaxf(rmax, __shfl_xor_sync(0xffffffffu, rmax, off));
        tmin = fminf(tmin, __shfl_xor_sync(0xffffffffu, tmin, off));
    }
    float lo = tmin, hi = rmax;
    float c_lo = 1024.0f, c_hi = 0.0f;    // counts at bracket ends

    // ---- count-based bisection, packed half2 compares + REDUX.SUM ----
    #pragma unroll
    for (int it = 0; it < NITER; ++it) {
        float T = 0.5f * (lo + hi);
        __half2 T2  = __float2half2_rn(T);
        __half2 acc = __float2half2_rn(0.0f);
        #pragma unroll
        for (int i = 0; i < H2N; i++)
            acc = __hadd2(acc, __hgt2(z2[i], T2));     // true -> 1.0
        int cnt = (int)(__low2float(acc) + __high2float(acc));
        cnt = __reduce_add_sync(0xffffffffu, cnt);
        if (cnt >= KSEL) { lo = T; c_lo = (float)cnt; }
        else             { hi = T; c_hi = (float)cnt; }
    }

    // ---- top-K sum: exact part above hi + boundary elems ~ interpolated T* ----
    {
        __half2 hi2  = __float2half2_rn(hi);
        __half2 sacc = __float2half2_rn(0.0f);
        __half2 cacc = __float2half2_rn(0.0f);
        #pragma unroll
        for (int i = 0; i < H2N; i++) {
            __half2 m = __hgt2(z2[i], hi2);
            sacc = __hfma2(m, z2[i], sacc);
            cacc = __hadd2(cacc, m);
        }
        float ssum = __low2float(sacc) + __high2float(sacc);
        int   chi  = (int)(__low2float(cacc) + __high2float(cacc));
        #pragma unroll
        for (int off = 16; off; off >>= 1)
            ssum += __shfl_xor_sync(0xffffffffu, ssum, off);
        chi = __reduce_add_sync(0xffffffffu, chi);

        // false-position estimate of the K-th order statistic inside [lo,hi]
        float Tk = lo + (hi - lo) * (c_lo - (float)KSEL)
                        * __fdividef(1.0f, fmaxf(c_lo - c_hi, 1.0f));
        Tk = fminf(fmaxf(Tk, lo), hi);

        float surp = (ssum + (float)(KSEL - chi) * Tk) * (1.0f / (float)KSEL);
        float gate = 1.0f + g_alpha * tanhf(g_sigma * surp);

        // ---- pass 2: GELU(x) * gate (x reloaded — L1 hit) ----
        const float inv_sqrt2 = 0.70710678118654752f;
        #pragma unroll
        for (int c = 0; c < CHUNKS; c++) {
            float4 xv = __ldg(xr + c * 32);
            float4 o;
            o.x = gate * xv.x * gelu_phi(xv.x);
            o.y = gate * xv.y * gelu_phi(xv.y);
            o.z = gate * xv.z * gelu_phi(xv.z);
            o.w = gate * xv.w * gelu_phi(xv.w);
            // rare deep-negative tail: exact erff to bound elementwise rel err
            float mn = fminf(fminf(xv.x, xv.y), fminf(xv.z, xv.w));
            if (mn < -3.5f) {
                if (xv.x < -3.5f) o.x = gate * 0.5f * xv.x * (1.0f + erff(xv.x * inv_sqrt2));
                if (xv.y < -3.5f) o.y = gate * 0.5f * xv.y * (1.0f + erff(xv.y * inv_sqrt2));
                if (xv.z < -3.5f) o.z = gate * 0.5f * xv.z * (1.0f + erff(xv.z * inv_sqrt2));
                if (xv.w < -3.5f) o.w = gate * 0.5f * xv.w * (1.0f + erff(xv.w * inv_sqrt2));
            }
            orow[c * 32] = o;
        }
    }
}

extern "C" void kernel_launch(void* const* d_in, const int* in_sizes, int n_in,
                              void* d_out, int out_size) {
    const float* x         = (const float*)d_in[0];
    const float* log_alpha = (const float*)d_in[1];
    const float* log_sigma = (const float*)d_in[2];
    const float* ema_mean  = (const float*)d_in[3];
    const float* ema_sq    = (const float*)d_in[4];
    float* out = (float*)d_out;

    int d    = in_sizes[3];          // 1024
    int rows = in_sizes[0] / d;      // 32768

    prep_kernel<<<(d + 255) / 256, 256>>>(ema_mean, ema_sq, log_alpha, log_sigma, d);

    int blocks = (rows + 7) / 8;     // 8 warps (rows) per 256-thread block
    gelu_topk_kernel<<<blocks, 256>>>(
        reinterpret_cast<const float4*>(x),
        reinterpret_cast<float4*>(out), rows);
}